// round 14
// baseline (speedup 1.0000x reference)
#include <cuda_runtime.h>
#include <cuda_bf16.h>
#include <cstdint>

// Problem constants (fixed by setup_inputs)
#define BATCH   8
#define S_LEN   1024
#define D_MODEL 1024
#define NH      16
#define DH      64
#define M_ROWS  (BATCH * S_LEN)   // 8192
#define DD      (D_MODEL * D_MODEL)
#define DU      (D_MODEL / 2)     // bf16x2 elements per row
#define MU      (M_ROWS * DU)     // elements per activation slab
#define SU2     (S_LEN / 2)       // key-pairs per sequence
#define RW      (2 * DU)          // u32 per interleaved row (1024)

// ---------------------------------------------------------------------------
// Scratch (device globals). All slabs store INTERLEAVED (hi,lo) u32 pairs:
// element e lives at u32 indices [2e] = hi, [2e+1] = lo.
// ---------------------------------------------------------------------------
__device__ uint32_t g_A2[3 * 2 * MU];    // raw q,k,v packed+split
__device__ uint32_t g_W2[4 * DD];        // Wq,Wk,Wv,Wo packed+split
__device__ uint32_t g_Q2[2 * MU];
__device__ uint32_t g_K2[2 * MU];
__device__ uint32_t g_Vt2[2 * MU];       // V transposed per (b,h): [dh][key-pair]
__device__ uint32_t g_O2[2 * MU];

// ---------------------------------------------------------------------------
// bf16 helpers (3xBF16: x = h + l; keep ah*bh + ah*bl + al*bh)
// ---------------------------------------------------------------------------
__device__ __forceinline__ uint32_t bpack(float x0, float x1) {
    __nv_bfloat162 t = __floats2bfloat162_rn(x0, x1);   // x0 -> low half
    return *reinterpret_cast<uint32_t*>(&t);
}
__device__ __forceinline__ void bsplit2(float x0, float x1, uint32_t& ph, uint32_t& pl) {
    const float h0 = __bfloat162float(__float2bfloat16(x0));
    const float h1 = __bfloat162float(__float2bfloat16(x1));
    ph = bpack(h0, h1);
    pl = bpack(x0 - h0, x1 - h1);
}
__device__ __forceinline__ void mma_bf16(float* c, const uint32_t* a, uint32_t b0, uint32_t b1) {
    asm volatile(
        "mma.sync.aligned.m16n8k16.row.col.f32.bf16.bf16.f32 "
        "{%0,%1,%2,%3}, {%4,%5,%6,%7}, {%8,%9}, {%0,%1,%2,%3};\n"
        : "+f"(c[0]), "+f"(c[1]), "+f"(c[2]), "+f"(c[3])
        : "r"(a[0]), "r"(a[1]), "r"(a[2]), "r"(a[3]), "r"(b0), "r"(b1));
}

// ---------------------------------------------------------------------------
// cp.async helpers
// ---------------------------------------------------------------------------
__device__ __forceinline__ void cpa16(uint32_t smaddr, const void* gptr) {
    asm volatile("cp.async.cg.shared.global [%0], [%1], 16;\n"
                 :: "r"(smaddr), "l"(gptr));
}
#define CP_COMMIT() asm volatile("cp.async.commit_group;\n" ::: "memory")
#define CP_WAIT1()  asm volatile("cp.async.wait_group 1;\n" ::: "memory")
#define CP_WAIT0()  asm volatile("cp.async.wait_group 0;\n" ::: "memory")

// ---------------------------------------------------------------------------
// Pre-split kernels (fp32 -> interleaved (hi,lo) bf16x2 slabs)
// ---------------------------------------------------------------------------
__global__ void split_weights_kernel(
    const float* __restrict__ W0, const float* __restrict__ W1,
    const float* __restrict__ W2, const float* __restrict__ W3,
    uint32_t* __restrict__ P2)
{
    const int z = blockIdx.y;
    const float* W = (z == 0) ? W0 : (z == 1) ? W1 : (z == 2) ? W2 : W3;
    const size_t fi = ((size_t)blockIdx.x * 256 + threadIdx.x) * 4;
    float4 x = *(const float4*)(W + fi);
    uint4 o;
    bsplit2(x.x, x.y, o.x, o.y);
    bsplit2(x.z, x.w, o.z, o.w);
    *(uint4*)(P2 + (size_t)z * DD + fi) = o;
}

__global__ void split_acts_kernel(
    const float* __restrict__ X0, const float* __restrict__ X1,
    const float* __restrict__ X2,
    uint32_t* __restrict__ P2)
{
    const int z = blockIdx.y;
    const float* X = (z == 0) ? X0 : (z == 1) ? X1 : X2;
    const size_t fi = ((size_t)blockIdx.x * 256 + threadIdx.x) * 4;
    float4 x = *(const float4*)(X + fi);
    uint4 o;
    bsplit2(x.x, x.y, o.x, o.y);
    bsplit2(x.z, x.w, o.z, o.w);
    *(uint4*)(P2 + (size_t)z * (2 * MU) + fi) = o;
}

// ---------------------------------------------------------------------------
// GEMM v8:  C = A @ W^T + bias, bf16x3, cp.async 2-stage, interleaved hi/lo
// (each fragment pair = one LDS.64; stride 40 u32 -> conflict-free per
// 16-lane phase: banks (8*gi + 2*t4) cover 16 even banks, +1 odd partners).
// Epilogue modes (QKV launch, outproj=0):
//   z=0 -> packed Q, z=1 -> packed K, z=2 -> packed V transposed.
// Out-proj launch (outproj=1): fp32 to Cout.
// ---------------------------------------------------------------------------
#define GBK 32              // bf16 elements per k-tile
#define GLD2 40             // u32 row stride in smem (payload 32)
#define T2 (128 * GLD2)     // 5120 u32 per tile
#define ST2 (2 * T2)        // 10240 u32 per stage (A + B)
#define G8_SMEM (2 * ST2 * 4)

__global__ void __launch_bounds__(256, 2) gemm8_bf16(
    const uint32_t* __restrict__ A2all, const uint32_t* __restrict__ W2all,
    const float* __restrict__ b0, const float* __restrict__ b1, const float* __restrict__ b2,
    uint32_t* __restrict__ Q2O, uint32_t* __restrict__ K2O, uint32_t* __restrict__ Vt2O,
    float* __restrict__ Cout,
    int widx0, int outproj)
{
    extern __shared__ uint32_t smu[];

    const int z = blockIdx.z;
    const float* bias = (z == 0) ? b0 : (z == 1) ? b1 : b2;
    const uint32_t* A2 = A2all + (size_t)z * (2 * MU);
    const uint32_t* B2 = W2all + (size_t)(widx0 + z) * DD;

    const int tid  = threadIdx.x;
    const int lane = tid & 31;
    const int warp = tid >> 5;
    const int wm = warp & 3;
    const int wn = warp >> 2;
    const int gi = lane >> 2;
    const int t4 = lane & 3;

    const int bm = blockIdx.y * 128;
    const int bn = blockIdx.x * 128;

    // loader: row = tid/2, 16 u32 at uc (4 x cp.async 16B per array)
    const int lr = tid >> 1;
    const int uc = (tid & 1) * 16;
    const uint32_t* Ag = A2 + (size_t)(bm + lr) * RW + uc;
    const uint32_t* Bg = B2 + (size_t)(bn + lr) * RW + uc;

    const uint32_t smbase = (uint32_t)__cvta_generic_to_shared(smu);
    const uint32_t rowoff = (lr * GLD2 + uc) * 4;

    float acc[2][8][4];
    #pragma unroll
    for (int mt = 0; mt < 2; mt++)
        #pragma unroll
        for (int nt = 0; nt < 8; nt++)
            #pragma unroll
            for (int i = 0; i < 4; i++) acc[mt][nt][i] = 0.0f;

    auto load_stage = [&](int st, int kt) {
        const int ku = kt * 32;   // u32 offset per k-tile
        const uint32_t sb = smbase + (uint32_t)st * (ST2 * 4) + rowoff;
        #pragma unroll
        for (int c = 0; c < 4; c++) {
            cpa16(sb + c * 16,          Ag + ku + c * 4);
            cpa16(sb + T2 * 4 + c * 16, Bg + ku + c * 4);
        }
    };

    const int ntiles = D_MODEL / GBK;   // 32
    load_stage(0, 0);
    CP_COMMIT();
    load_stage(1, 1);
    CP_COMMIT();

    for (int i = 0; i < ntiles; i++) {
        if (i + 1 < ntiles) CP_WAIT1(); else CP_WAIT0();
        __syncthreads();

        const uint32_t* S  = smu + (i & 1) * ST2;
        const uint32_t* SA = S;
        const uint32_t* SB = S + T2;

        #pragma unroll
        for (int kk = 0; kk < 2; kk++) {          // two k16 steps
            const int ec = kk * 8;                // element col base
            uint32_t ah[2][4], al[2][4];
            #pragma unroll
            for (int mt = 0; mt < 2; mt++) {
                const int r = wm * 32 + mt * 16 + gi;
                uint2 p;
                p = *(const uint2*)&SA[r * GLD2 + 2 * (ec + t4)];
                ah[mt][0] = p.x; al[mt][0] = p.y;
                p = *(const uint2*)&SA[(r + 8) * GLD2 + 2 * (ec + t4)];
                ah[mt][1] = p.x; al[mt][1] = p.y;
                p = *(const uint2*)&SA[r * GLD2 + 2 * (ec + t4 + 4)];
                ah[mt][2] = p.x; al[mt][2] = p.y;
                p = *(const uint2*)&SA[(r + 8) * GLD2 + 2 * (ec + t4 + 4)];
                ah[mt][3] = p.x; al[mt][3] = p.y;
            }
            #pragma unroll
            for (int nt = 0; nt < 8; nt++) {
                const int rb = wn * 64 + nt * 8 + gi;
                const uint2 pb0 = *(const uint2*)&SB[rb * GLD2 + 2 * (ec + t4)];
                const uint2 pb1 = *(const uint2*)&SB[rb * GLD2 + 2 * (ec + t4 + 4)];
                #pragma unroll
                for (int mt = 0; mt < 2; mt++) {
                    mma_bf16(acc[mt][nt], al[mt], pb0.x, pb1.x);
                    mma_bf16(acc[mt][nt], ah[mt], pb0.y, pb1.y);
                    mma_bf16(acc[mt][nt], ah[mt], pb0.x, pb1.x);
                }
            }
        }

        __syncthreads();
        if (i + 2 < ntiles) {
            load_stage(i & 1, i + 2);
            CP_COMMIT();
        }
    }

    // ---------------- epilogue ----------------
    if (outproj) {
        #pragma unroll
        for (int nt = 0; nt < 8; nt++) {
            const int col = bn + wn * 64 + nt * 8 + 2 * t4;
            const float2 bb = *(const float2*)(bias + col);
            #pragma unroll
            for (int mt = 0; mt < 2; mt++) {
                const int row0 = bm + wm * 32 + mt * 16 + gi;
                float2 o0, o1;
                o0.x = acc[mt][nt][0] + bb.x; o0.y = acc[mt][nt][1] + bb.y;
                o1.x = acc[mt][nt][2] + bb.x; o1.y = acc[mt][nt][3] + bb.y;
                *(float2*)(Cout + (size_t)row0 * D_MODEL + col)       = o0;
                *(float2*)(Cout + (size_t)(row0 + 8) * D_MODEL + col) = o1;
            }
        }
    } else if (z < 2) {
        uint32_t* Ho = (z == 0) ? Q2O : K2O;
        #pragma unroll
        for (int nt = 0; nt < 8; nt++) {
            const int col = bn + wn * 64 + nt * 8 + 2 * t4;   // even
            const float2 bb = *(const float2*)(bias + col);
            #pragma unroll
            for (int mt = 0; mt < 2; mt++) {
                const int row0 = bm + wm * 32 + mt * 16 + gi;
                uint2 o;
                bsplit2(acc[mt][nt][0] + bb.x, acc[mt][nt][1] + bb.y, o.x, o.y);
                *(uint2*)(Ho + (size_t)row0 * RW + col) = o;
                bsplit2(acc[mt][nt][2] + bb.x, acc[mt][nt][3] + bb.y, o.x, o.y);
                *(uint2*)(Ho + (size_t)(row0 + 8) * RW + col) = o;
            }
        }
    } else {
        // V: transposed packed per (b,h): [dh][key-pair], interleaved
        #pragma unroll
        for (int nt = 0; nt < 8; nt++) {
            const int cg = bn + wn * 64 + nt * 8 + 2 * t4;
            const float2 bb = *(const float2*)(bias + cg);
            #pragma unroll
            for (int mt = 0; mt < 2; mt++) {
                const int r = bm + wm * 32 + mt * 16 + gi;
                const float c0 = acc[mt][nt][0] + bb.x;
                const float c1 = acc[mt][nt][1] + bb.y;
                const float c2 = acc[mt][nt][2] + bb.x;
                const float c3 = acc[mt][nt][3] + bb.y;
                const float p0 = __shfl_xor_sync(0xffffffffu, c0, 4);
                const float p1 = __shfl_xor_sync(0xffffffffu, c1, 4);
                const float p2 = __shfl_xor_sync(0xffffffffu, c2, 4);
                const float p3 = __shfl_xor_sync(0xffffffffu, c3, 4);
                uint2 o;
                if ((gi & 1) == 0) {
                    const int bb_ = r >> 10, s = r & 1023;
                    const int h_ = cg >> 6, dh = cg & 63;
                    const size_t pe = ((size_t)(bb_ * NH + h_) * DH + dh) * SU2 + (s >> 1);
                    bsplit2(c0, p0, o.x, o.y);
                    *(uint2*)(Vt2O + 2 * pe) = o;
                    bsplit2(c2, p2, o.x, o.y);
                    *(uint2*)(Vt2O + 2 * (pe + 4)) = o;
                } else {
                    const int rr = r - 1;
                    const int bb_ = rr >> 10, s = rr & 1023;
                    const int h_ = (cg + 1) >> 6, dh = (cg + 1) & 63;
                    const size_t pe = ((size_t)(bb_ * NH + h_) * DH + dh) * SU2 + (s >> 1);
                    bsplit2(p1, c1, o.x, o.y);
                    *(uint2*)(Vt2O + 2 * pe) = o;
                    bsplit2(p3, c3, o.x, o.y);
                    *(uint2*)(Vt2O + 2 * (pe + 4)) = o;
                }
            }
        }
    }
}

// ---------------------------------------------------------------------------
// Flash attention v7: bf16x3, interleaved hi/lo operands (LDS.64 fragments),
// register-direct P, cp.async 2-stage tiles.
// Smem stride 72 u32: banks (8*row + 2*col) per 16-lane phase conflict-free.
// ---------------------------------------------------------------------------
#define LDK2 72
#define AT_T (64 * LDK2)      // 4608 u32 per tile
#define AT_S (2 * AT_T)       // 9216 u32 per stage (K + V)
#define AT_MSK (2 * AT_S)     // 18432
#define AT_SMEM ((AT_MSK + 32) * 4)

__global__ void __launch_bounds__(256, 1) attn_bf16_kernel(
    const uint32_t* __restrict__ Q2, const uint32_t* __restrict__ K2,
    const uint32_t* __restrict__ Vt2,
    const unsigned char* __restrict__ kpm,
    uint32_t* __restrict__ O2)
{
    extern __shared__ uint32_t su[];

    const int b   = blockIdx.z;
    const int h   = blockIdx.y;
    const int qt  = gridDim.x - 1 - blockIdx.x;   // heavy tiles first
    const int tid = threadIdx.x;
    const int w    = tid >> 5;
    const int lane = tid & 31;
    const int gi = lane >> 2;
    const int t4 = lane & 3;

    const int q0   = qt * 128;
    const int row0 = q0 + w * 16 + gi;

    const float scale = 0.125f;
    const float NEG = -1e30f;

    // ---- Q fragments: u64 loads from interleaved slab ----
    uint32_t qh[4][4], ql[4][4];
    {
        const uint32_t* qb0 = Q2 + (size_t)(b * S_LEN + row0) * RW + h * 64;
        const uint32_t* qb1 = qb0 + 8 * RW;
        #pragma unroll
        for (int kc = 0; kc < 4; kc++) {
            uint2 p;
            p = *(const uint2*)(qb0 + 2 * (kc * 8 + t4));
            qh[kc][0] = p.x; ql[kc][0] = p.y;
            p = *(const uint2*)(qb1 + 2 * (kc * 8 + t4));
            qh[kc][1] = p.x; ql[kc][1] = p.y;
            p = *(const uint2*)(qb0 + 2 * (kc * 8 + t4 + 4));
            qh[kc][2] = p.x; ql[kc][2] = p.y;
            p = *(const uint2*)(qb1 + 2 * (kc * 8 + t4 + 4));
            qh[kc][3] = p.x; ql[kc][3] = p.y;
        }
    }

    float oc[8][4];
    #pragma unroll
    for (int nt = 0; nt < 8; nt++)
        #pragma unroll
        for (int i = 0; i < 4; i++) oc[nt][i] = 0.0f;
    float m0 = NEG, m1 = NEG, l0 = 0.0f, l1 = 0.0f;

    // tile loader: row = tid>>2 (0..63), seg = tid&3 (16 u32 each)
    const int ldr = tid >> 2;
    const int seg = tid & 3;
    const uint32_t smbase = (uint32_t)__cvta_generic_to_shared(su);
    const uint32_t dsto = (uint32_t)(ldr * LDK2 + seg * 16) * 4;

    const uint32_t* kg = K2 + (size_t)(b * S_LEN + ldr) * RW + h * 64 + seg * 16;
    const uint32_t* vg = Vt2 + ((size_t)(b * NH + h) * DH + ldr) * RW + seg * 16;

    auto load_tile = [&](int st, int kt) {
        const int k0 = kt * 64;
        const uint32_t sb = smbase + (uint32_t)st * (AT_S * 4) + dsto;
        const uint32_t* kgk = kg + (size_t)k0 * RW;
        const uint32_t* vgk = vg + k0;      // key-pair k0/2 -> u32 offset k0
        #pragma unroll
        for (int c = 0; c < 4; c++) {
            cpa16(sb + c * 16,            kgk + c * 4);
            cpa16(sb + AT_T * 4 + c * 16, vgk + c * 4);
        }
        if (tid < 4)
            cpa16(smbase + (AT_MSK + st * 16) * 4 + tid * 16,
                  kpm + (size_t)b * S_LEN + k0 + tid * 16);
    };

    const int ktiles = 2 * qt + 2;

    load_tile(0, 0);
    CP_COMMIT();
    load_tile(1, 1);
    CP_COMMIT();

    for (int kt = 0; kt < ktiles; kt++) {
        const int k0 = kt * 64;
        if (kt + 1 < ktiles) CP_WAIT1(); else CP_WAIT0();
        __syncthreads();

        const uint32_t* St = su + (kt & 1) * AT_S;
        const uint32_t* Ks = St;
        const uint32_t* Vs = St + AT_T;
        const unsigned char* mb = (const unsigned char*)(su + AT_MSK + (kt & 1) * 16);

        // ---- S = Q K^T (bf16 x3) ----
        float sc[8][4];
        #pragma unroll
        for (int nt = 0; nt < 8; nt++)
            #pragma unroll
            for (int i = 0; i < 4; i++) sc[nt][i] = 0.0f;

        #pragma unroll
        for (int kc = 0; kc < 4; kc++) {
            uint32_t bh[8][2], bl[8][2];
            #pragma unroll
            for (int nt = 0; nt < 8; nt++) {
                const int base = (nt * 8 + gi) * LDK2 + 2 * (kc * 8 + t4);
                const uint2 p0 = *(const uint2*)&Ks[base];
                const uint2 p1 = *(const uint2*)&Ks[base + 8];
                bh[nt][0] = p0.x; bl[nt][0] = p0.y;
                bh[nt][1] = p1.x; bl[nt][1] = p1.y;
            }
            #pragma unroll
            for (int nt = 0; nt < 8; nt++) mma_bf16(sc[nt], ql[kc], bh[nt][0], bh[nt][1]);
            #pragma unroll
            for (int nt = 0; nt < 8; nt++) mma_bf16(sc[nt], qh[kc], bl[nt][0], bl[nt][1]);
            #pragma unroll
            for (int nt = 0; nt < 8; nt++) mma_bf16(sc[nt], qh[kc], bh[nt][0], bh[nt][1]);
        }

        // ---- scale + masks + online softmax ----
        const bool needc = (k0 + 63) > row0;
        float rm0 = NEG, rm1 = NEG;
        #pragma unroll
        for (int nt = 0; nt < 8; nt++) {
            const int col = k0 + nt * 8 + 2 * t4;
            const float mg0 = mb[nt * 8 + 2 * t4]     ? NEG : 0.0f;
            const float mg1 = mb[nt * 8 + 2 * t4 + 1] ? NEG : 0.0f;
            float v0 = sc[nt][0] * scale + mg0;
            float v1 = sc[nt][1] * scale + mg1;
            float v2 = sc[nt][2] * scale + mg0;
            float v3 = sc[nt][3] * scale + mg1;
            if (needc) {
                if (col     > row0)     v0 = NEG;
                if (col + 1 > row0)     v1 = NEG;
                if (col     > row0 + 8) v2 = NEG;
                if (col + 1 > row0 + 8) v3 = NEG;
            }
            sc[nt][0] = v0; sc[nt][1] = v1; sc[nt][2] = v2; sc[nt][3] = v3;
            rm0 = fmaxf(rm0, fmaxf(v0, v1));
            rm1 = fmaxf(rm1, fmaxf(v2, v3));
        }
        rm0 = fmaxf(rm0, __shfl_xor_sync(0xffffffffu, rm0, 1, 4));
        rm0 = fmaxf(rm0, __shfl_xor_sync(0xffffffffu, rm0, 2, 4));
        rm1 = fmaxf(rm1, __shfl_xor_sync(0xffffffffu, rm1, 1, 4));
        rm1 = fmaxf(rm1, __shfl_xor_sync(0xffffffffu, rm1, 2, 4));

        const float mn0 = fmaxf(m0, rm0);
        const float mn1 = fmaxf(m1, rm1);
        const float cr0 = __expf(m0 - mn0);
        const float cr1 = __expf(m1 - mn1);

        float ps0 = 0.0f, ps1 = 0.0f;
        #pragma unroll
        for (int nt = 0; nt < 8; nt++) {
            const float e0 = __expf(sc[nt][0] - mn0);
            const float e1 = __expf(sc[nt][1] - mn0);
            const float e2 = __expf(sc[nt][2] - mn1);
            const float e3 = __expf(sc[nt][3] - mn1);
            sc[nt][0] = e0; sc[nt][1] = e1; sc[nt][2] = e2; sc[nt][3] = e3;
            ps0 += e0 + e1;
            ps1 += e2 + e3;
        }
        ps0 += __shfl_xor_sync(0xffffffffu, ps0, 1, 4);
        ps0 += __shfl_xor_sync(0xffffffffu, ps0, 2, 4);
        ps1 += __shfl_xor_sync(0xffffffffu, ps1, 1, 4);
        ps1 += __shfl_xor_sync(0xffffffffu, ps1, 2, 4);

        l0 = l0 * cr0 + ps0;  m0 = mn0;
        l1 = l1 * cr1 + ps1;  m1 = mn1;

        #pragma unroll
        for (int nt = 0; nt < 8; nt++) {
            oc[nt][0] *= cr0; oc[nt][1] *= cr0;
            oc[nt][2] *= cr1; oc[nt][3] *= cr1;
        }

        // ---- O += P V (bf16 x3): P fragments built directly in registers ----
        #pragma unroll
        for (int kc = 0; kc < 4; kc++) {
            uint32_t ah[4], al[4];
            bsplit2(sc[2 * kc][0],     sc[2 * kc][1],     ah[0], al[0]);
            bsplit2(sc[2 * kc][2],     sc[2 * kc][3],     ah[1], al[1]);
            bsplit2(sc[2 * kc + 1][0], sc[2 * kc + 1][1], ah[2], al[2]);
            bsplit2(sc[2 * kc + 1][2], sc[2 * kc + 1][3], ah[3], al[3]);

            uint32_t bh[8][2], bl[8][2];
            #pragma unroll
            for (int nt = 0; nt < 8; nt++) {
                const int base = (nt * 8 + gi) * LDK2 + 2 * (kc * 8 + t4);
                const uint2 p0 = *(const uint2*)&Vs[base];
                const uint2 p1 = *(const uint2*)&Vs[base + 8];
                bh[nt][0] = p0.x; bl[nt][0] = p0.y;
                bh[nt][1] = p1.x; bl[nt][1] = p1.y;
            }
            #pragma unroll
            for (int nt = 0; nt < 8; nt++) mma_bf16(oc[nt], al, bh[nt][0], bh[nt][1]);
            #pragma unroll
            for (int nt = 0; nt < 8; nt++) mma_bf16(oc[nt], ah, bl[nt][0], bl[nt][1]);
            #pragma unroll
            for (int nt = 0; nt < 8; nt++) mma_bf16(oc[nt], ah, bh[nt][0], bh[nt][1]);
        }

        __syncthreads();
        if (kt + 2 < ktiles) {
            load_tile(kt & 1, kt + 2);
            CP_COMMIT();
        }
    }

    // ---- normalize + store interleaved ----
    const float inv0 = 1.0f / l0;
    const float inv1 = 1.0f / l1;
    uint32_t* ob0 = O2 + (size_t)(b * S_LEN + row0) * RW + h * 64;
    uint32_t* ob1 = ob0 + 8 * RW;
    #pragma unroll
    for (int nt = 0; nt < 8; nt++) {
        uint2 o;
        bsplit2(oc[nt][0] * inv0, oc[nt][1] * inv0, o.x, o.y);
        *(uint2*)(ob0 + 2 * (nt * 4 + t4)) = o;
        bsplit2(oc[nt][2] * inv1, oc[nt][3] * inv1, o.x, o.y);
        *(uint2*)(ob1 + 2 * (nt * 4 + t4)) = o;
    }
}

// ---------------------------------------------------------------------------
// Launch
// ---------------------------------------------------------------------------
extern "C" void kernel_launch(void* const* d_in, const int* in_sizes, int n_in,
                              void* d_out, int out_size)
{
    const float* q    = (const float*)d_in[0];
    const float* k    = (const float*)d_in[1];
    const float* v    = (const float*)d_in[2];
    const unsigned char* kpm = (const unsigned char*)d_in[3];
    const float* Wq = (const float*)d_in[4];
    const float* bq = (const float*)d_in[5];
    const float* Wk = (const float*)d_in[6];
    const float* bk = (const float*)d_in[7];
    const float* Wv = (const float*)d_in[8];
    const float* bv = (const float*)d_in[9];
    const float* Wo = (const float*)d_in[10];
    const float* bo = (const float*)d_in[11];
    float* out = (float*)d_out;

    void *pA2, *pW2, *pQ2, *pK2, *pVt2, *pO2;
    cudaGetSymbolAddress(&pA2, g_A2);
    cudaGetSymbolAddress(&pW2, g_W2);
    cudaGetSymbolAddress(&pQ2, g_Q2);
    cudaGetSymbolAddress(&pK2, g_K2);
    cudaGetSymbolAddress(&pVt2, g_Vt2);
    cudaGetSymbolAddress(&pO2, g_O2);

    cudaFuncSetAttribute(attn_bf16_kernel,
                         cudaFuncAttributeMaxDynamicSharedMemorySize, AT_SMEM);
    cudaFuncSetAttribute(gemm8_bf16,
                         cudaFuncAttributeMaxDynamicSharedMemorySize, G8_SMEM);

    // 1) pre-split weights + raw q/k/v activations (interleaved hi/lo)
    dim3 wgrid(DD / 1024, 4);
    split_weights_kernel<<<wgrid, 256>>>(Wq, Wk, Wv, Wo, (uint32_t*)pW2);
    dim3 sgrid((M_ROWS * D_MODEL) / 1024, 3);
    split_acts_kernel<<<sgrid, 256>>>(q, k, v, (uint32_t*)pA2);

    // 2) fused Q/K/V projections -> packed (V transposed)
    dim3 ggrid(D_MODEL / 128, M_ROWS / 128, 3);
    gemm8_bf16<<<ggrid, 256, G8_SMEM>>>(
        (const uint32_t*)pA2, (const uint32_t*)pW2,
        bq, bk, bv,
        (uint32_t*)pQ2, (uint32_t*)pK2, (uint32_t*)pVt2,
        nullptr, 0, 0);

    // 3) attention -> packed Ao (interleaved)
    dim3 agrid(S_LEN / 128, NH, BATCH);
    attn_bf16_kernel<<<agrid, 256, AT_SMEM>>>(
        (const uint32_t*)pQ2, (const uint32_t*)pK2, (const uint32_t*)pVt2,
        kpm, (uint32_t*)pO2);

    // 4) output projection (weight slab 3) -> fp32 out
    dim3 ogrid(D_MODEL / 128, M_ROWS / 128, 1);
    gemm8_bf16<<<ogrid, 256, G8_SMEM>>>(
        (const uint32_t*)pO2, (const uint32_t*)pW2,
        bo, bo, bo,
        nullptr, nullptr, nullptr,
        out, 3, 1);
}

// round 15
// speedup vs baseline: 1.2240x; 1.2240x over previous
#include <cuda_runtime.h>
#include <cuda_bf16.h>
#include <cstdint>

// Problem constants (fixed by setup_inputs)
#define BATCH   8
#define S_LEN   1024
#define D_MODEL 1024
#define NH      16
#define DH      64
#define M_ROWS  (BATCH * S_LEN)   // 8192
#define DD      (D_MODEL * D_MODEL)
#define DU      (D_MODEL / 2)     // u32 (bf16x2) per row
#define MU      (M_ROWS * DU)     // u32 per activation slab
#define SU2     (S_LEN / 2)       // key-pairs per sequence

// ---------------------------------------------------------------------------
// Scratch (device globals — no allocations allowed)
// ---------------------------------------------------------------------------
__device__ uint32_t g_Ahp[3 * MU];
__device__ uint32_t g_Alp[3 * MU];
__device__ uint32_t g_Whp[4 * DD / 2];
__device__ uint32_t g_Wlp[4 * DD / 2];
__device__ uint32_t g_Qh[MU], g_Ql[MU];
__device__ uint32_t g_Kh[MU], g_Kl[MU];
__device__ uint32_t g_VtH[MU], g_VtL[MU];   // V transposed per (b,h): [dh][key-pair]
__device__ uint32_t g_Oh[MU], g_Ol[MU];

// ---------------------------------------------------------------------------
// bf16 helpers (3xBF16: x = h + l; keep ah*bh + ah*bl + al*bh)
// ---------------------------------------------------------------------------
__device__ __forceinline__ uint32_t bpack(float x0, float x1) {
    __nv_bfloat162 t = __floats2bfloat162_rn(x0, x1);   // x0 -> low half
    return *reinterpret_cast<uint32_t*>(&t);
}
__device__ __forceinline__ void bsplit2(float x0, float x1, uint32_t& ph, uint32_t& pl) {
    const float h0 = __bfloat162float(__float2bfloat16(x0));
    const float h1 = __bfloat162float(__float2bfloat16(x1));
    ph = bpack(h0, h1);
    pl = bpack(x0 - h0, x1 - h1);
}
__device__ __forceinline__ void mma_bf16(float* c, const uint32_t* a, uint32_t b0, uint32_t b1) {
    asm volatile(
        "mma.sync.aligned.m16n8k16.row.col.f32.bf16.bf16.f32 "
        "{%0,%1,%2,%3}, {%4,%5,%6,%7}, {%8,%9}, {%0,%1,%2,%3};\n"
        : "+f"(c[0]), "+f"(c[1]), "+f"(c[2]), "+f"(c[3])
        : "r"(a[0]), "r"(a[1]), "r"(a[2]), "r"(a[3]), "r"(b0), "r"(b1));
}

// ---------------------------------------------------------------------------
// cp.async helpers
// ---------------------------------------------------------------------------
__device__ __forceinline__ void cpa16(uint32_t smaddr, const void* gptr) {
    asm volatile("cp.async.cg.shared.global [%0], [%1], 16;\n"
                 :: "r"(smaddr), "l"(gptr));
}
#define CP_COMMIT() asm volatile("cp.async.commit_group;\n" ::: "memory")
#define CP_WAIT1()  asm volatile("cp.async.wait_group 1;\n" ::: "memory")
#define CP_WAIT0()  asm volatile("cp.async.wait_group 0;\n" ::: "memory")

// ---------------------------------------------------------------------------
// Pre-split kernels (fp32 -> packed bf16x2 hi/lo)
// ---------------------------------------------------------------------------
__global__ void split_weights_kernel(
    const float* __restrict__ W0, const float* __restrict__ W1,
    const float* __restrict__ W2, const float* __restrict__ W3,
    uint32_t* __restrict__ Hp, uint32_t* __restrict__ Lp)
{
    const int z = blockIdx.y;
    const float* W = (z == 0) ? W0 : (z == 1) ? W1 : (z == 2) ? W2 : W3;
    const size_t fi = ((size_t)blockIdx.x * 256 + threadIdx.x) * 4;
    const size_t ui = (size_t)z * (DD / 2) + fi / 2;
    float4 x = *(const float4*)(W + fi);
    uint2 h2, l2;
    bsplit2(x.x, x.y, h2.x, l2.x);
    bsplit2(x.z, x.w, h2.y, l2.y);
    *(uint2*)(Hp + ui) = h2;
    *(uint2*)(Lp + ui) = l2;
}

__global__ void split_acts_kernel(
    const float* __restrict__ X0, const float* __restrict__ X1,
    const float* __restrict__ X2,
    uint32_t* __restrict__ Hp, uint32_t* __restrict__ Lp)
{
    const int z = blockIdx.y;
    const float* X = (z == 0) ? X0 : (z == 1) ? X1 : X2;
    const size_t fi = ((size_t)blockIdx.x * 256 + threadIdx.x) * 4;
    const size_t ui = (size_t)z * MU + fi / 2;
    float4 x = *(const float4*)(X + fi);
    uint2 h2, l2;
    bsplit2(x.x, x.y, h2.x, l2.x);
    bsplit2(x.z, x.w, h2.y, l2.y);
    *(uint2*)(Hp + ui) = h2;
    *(uint2*)(Lp + ui) = l2;
}

// ---------------------------------------------------------------------------
// GEMM v9:  C = A @ W^T + bias, bf16x3, cp.async 2-stage, scalar LDS
// fragments (round-10 layout), but the mma inner loop is TERM-MAJOR over
// nt-halves of 4: 8 independent mma's between touches of the same
// accumulator (was 3 back-to-back RAW-dependent mma's). Per-accumulator op
// order unchanged (albh, ahbl, ahbh per k16) -> bit-identical numerics.
// ---------------------------------------------------------------------------
#define GBK 32
#define GKU 16
#define GLD 20
#define TILE_U32 (128 * GLD)
#define STAGE_U32 (4 * TILE_U32)
#define G4_SMEM (2 * STAGE_U32 * 4)

__global__ void __launch_bounds__(256, 2) gemm9_bf16(
    const uint32_t* __restrict__ Ahp, const uint32_t* __restrict__ Alp,
    const uint32_t* __restrict__ Whp, const uint32_t* __restrict__ Wlp,
    const float* __restrict__ b0, const float* __restrict__ b1, const float* __restrict__ b2,
    uint32_t* __restrict__ QhO, uint32_t* __restrict__ QlO,
    uint32_t* __restrict__ KhO, uint32_t* __restrict__ KlO,
    uint32_t* __restrict__ VtHO, uint32_t* __restrict__ VtLO,
    float* __restrict__ Cout,
    int widx0, int outproj)
{
    extern __shared__ uint32_t smu[];

    const int z = blockIdx.z;
    const float* bias = (z == 0) ? b0 : (z == 1) ? b1 : b2;
    const uint32_t* Ah = Ahp + (size_t)z * MU;
    const uint32_t* Al = Alp + (size_t)z * MU;
    const uint32_t* Bh = Whp + (size_t)(widx0 + z) * (DD / 2);
    const uint32_t* Bl = Wlp + (size_t)(widx0 + z) * (DD / 2);

    const int tid  = threadIdx.x;
    const int lane = tid & 31;
    const int warp = tid >> 5;
    const int wm = warp & 3;
    const int wn = warp >> 2;
    const int gi = lane >> 2;
    const int t4 = lane & 3;

    const int bm = blockIdx.y * 128;
    const int bn = blockIdx.x * 128;

    const int lr = tid >> 1;
    const int uc = (tid & 1) * 8;
    const uint32_t* Ahg = Ah + (size_t)(bm + lr) * DU + uc;
    const uint32_t* Alg = Al + (size_t)(bm + lr) * DU + uc;
    const uint32_t* Bhg = Bh + (size_t)(bn + lr) * DU + uc;
    const uint32_t* Blg = Bl + (size_t)(bn + lr) * DU + uc;

    const uint32_t smbase = (uint32_t)__cvta_generic_to_shared(smu);
    const uint32_t rowoff = (lr * GLD + uc) * 4;

    float acc[2][8][4];
    #pragma unroll
    for (int mt = 0; mt < 2; mt++)
        #pragma unroll
        for (int nt = 0; nt < 8; nt++)
            #pragma unroll
            for (int i = 0; i < 4; i++) acc[mt][nt][i] = 0.0f;

    auto load_stage = [&](int st, int k0) {
        const int ku = k0 >> 1;
        const uint32_t sb = smbase + (uint32_t)st * (STAGE_U32 * 4) + rowoff;
        cpa16(sb,                      Ahg + ku);
        cpa16(sb + 16,                 Ahg + ku + 4);
        cpa16(sb + TILE_U32 * 4,       Alg + ku);
        cpa16(sb + TILE_U32 * 4 + 16,  Alg + ku + 4);
        cpa16(sb + TILE_U32 * 8,       Bhg + ku);
        cpa16(sb + TILE_U32 * 8 + 16,  Bhg + ku + 4);
        cpa16(sb + TILE_U32 * 12,      Blg + ku);
        cpa16(sb + TILE_U32 * 12 + 16, Blg + ku + 4);
    };

    const int ntiles = D_MODEL / GBK;
    load_stage(0, 0);
    CP_COMMIT();
    load_stage(1, GBK);
    CP_COMMIT();

    for (int i = 0; i < ntiles; i++) {
        if (i + 1 < ntiles) CP_WAIT1(); else CP_WAIT0();
        __syncthreads();

        const uint32_t* S   = smu + (i & 1) * STAGE_U32;
        const uint32_t* Ash = S;
        const uint32_t* Asl = S + TILE_U32;
        const uint32_t* Bsh = S + 2 * TILE_U32;
        const uint32_t* Bsl = S + 3 * TILE_U32;

        #pragma unroll
        for (int kk = 0; kk < GKU; kk += 8) {
            uint32_t ah[2][4], al[2][4];
            #pragma unroll
            for (int mt = 0; mt < 2; mt++) {
                const int r = wm * 32 + mt * 16 + gi;
                ah[mt][0] = Ash[r * GLD + kk + t4];
                al[mt][0] = Asl[r * GLD + kk + t4];
                ah[mt][1] = Ash[(r + 8) * GLD + kk + t4];
                al[mt][1] = Asl[(r + 8) * GLD + kk + t4];
                ah[mt][2] = Ash[r * GLD + kk + t4 + 4];
                al[mt][2] = Asl[r * GLD + kk + t4 + 4];
                ah[mt][3] = Ash[(r + 8) * GLD + kk + t4 + 4];
                al[mt][3] = Asl[(r + 8) * GLD + kk + t4 + 4];
            }
            // nt-halves of 4, term-major: dependency distance per acc = 8 mma
            #pragma unroll
            for (int nh = 0; nh < 2; nh++) {
                uint32_t bh[4][2], bl[4][2];
                #pragma unroll
                for (int j = 0; j < 4; j++) {
                    const int rb = wn * 64 + (nh * 4 + j) * 8 + gi;
                    bh[j][0] = Bsh[rb * GLD + kk + t4];
                    bh[j][1] = Bsh[rb * GLD + kk + t4 + 4];
                    bl[j][0] = Bsl[rb * GLD + kk + t4];
                    bl[j][1] = Bsl[rb * GLD + kk + t4 + 4];
                }
                #pragma unroll
                for (int j = 0; j < 4; j++)
                    #pragma unroll
                    for (int mt = 0; mt < 2; mt++)
                        mma_bf16(acc[mt][nh * 4 + j], al[mt], bh[j][0], bh[j][1]);
                #pragma unroll
                for (int j = 0; j < 4; j++)
                    #pragma unroll
                    for (int mt = 0; mt < 2; mt++)
                        mma_bf16(acc[mt][nh * 4 + j], ah[mt], bl[j][0], bl[j][1]);
                #pragma unroll
                for (int j = 0; j < 4; j++)
                    #pragma unroll
                    for (int mt = 0; mt < 2; mt++)
                        mma_bf16(acc[mt][nh * 4 + j], ah[mt], bh[j][0], bh[j][1]);
            }
        }

        __syncthreads();
        if (i + 2 < ntiles) {
            load_stage(i & 1, (i + 2) * GBK);
            CP_COMMIT();
        }
    }

    // ---------------- epilogue ----------------
    if (outproj) {
        #pragma unroll
        for (int nt = 0; nt < 8; nt++) {
            const int col = bn + wn * 64 + nt * 8 + 2 * t4;
            const float2 bb = *(const float2*)(bias + col);
            #pragma unroll
            for (int mt = 0; mt < 2; mt++) {
                const int row0 = bm + wm * 32 + mt * 16 + gi;
                float2 o0, o1;
                o0.x = acc[mt][nt][0] + bb.x; o0.y = acc[mt][nt][1] + bb.y;
                o1.x = acc[mt][nt][2] + bb.x; o1.y = acc[mt][nt][3] + bb.y;
                *(float2*)(Cout + (size_t)row0 * D_MODEL + col)       = o0;
                *(float2*)(Cout + (size_t)(row0 + 8) * D_MODEL + col) = o1;
            }
        }
    } else if (z < 2) {
        uint32_t* Ho = (z == 0) ? QhO : KhO;
        uint32_t* Lo = (z == 0) ? QlO : KlO;
        #pragma unroll
        for (int nt = 0; nt < 8; nt++) {
            const int col  = bn + wn * 64 + nt * 8 + 2 * t4;
            const int colu = col >> 1;
            const float2 bb = *(const float2*)(bias + col);
            #pragma unroll
            for (int mt = 0; mt < 2; mt++) {
                const int row0 = bm + wm * 32 + mt * 16 + gi;
                uint32_t ph, pl;
                bsplit2(acc[mt][nt][0] + bb.x, acc[mt][nt][1] + bb.y, ph, pl);
                Ho[(size_t)row0 * DU + colu] = ph;
                Lo[(size_t)row0 * DU + colu] = pl;
                bsplit2(acc[mt][nt][2] + bb.x, acc[mt][nt][3] + bb.y, ph, pl);
                Ho[(size_t)(row0 + 8) * DU + colu] = ph;
                Lo[(size_t)(row0 + 8) * DU + colu] = pl;
            }
        }
    } else {
        // V: transposed packed per (b,h): [dh][key-pair]
        #pragma unroll
        for (int nt = 0; nt < 8; nt++) {
            const int cg = bn + wn * 64 + nt * 8 + 2 * t4;
            const float2 bb = *(const float2*)(bias + cg);
            #pragma unroll
            for (int mt = 0; mt < 2; mt++) {
                const int r = bm + wm * 32 + mt * 16 + gi;
                const float c0 = acc[mt][nt][0] + bb.x;
                const float c1 = acc[mt][nt][1] + bb.y;
                const float c2 = acc[mt][nt][2] + bb.x;
                const float c3 = acc[mt][nt][3] + bb.y;
                const float p0 = __shfl_xor_sync(0xffffffffu, c0, 4);
                const float p1 = __shfl_xor_sync(0xffffffffu, c1, 4);
                const float p2 = __shfl_xor_sync(0xffffffffu, c2, 4);
                const float p3 = __shfl_xor_sync(0xffffffffu, c3, 4);
                uint32_t ph, pl;
                if ((gi & 1) == 0) {
                    const int bb_ = r >> 10, s = r & 1023;
                    const int h_ = cg >> 6, dh = cg & 63;
                    const size_t plane = ((size_t)(bb_ * NH + h_) * DH + dh) * SU2;
                    bsplit2(c0, p0, ph, pl);
                    VtHO[plane + (s >> 1)] = ph;
                    VtLO[plane + (s >> 1)] = pl;
                    bsplit2(c2, p2, ph, pl);
                    VtHO[plane + (s >> 1) + 4] = ph;
                    VtLO[plane + (s >> 1) + 4] = pl;
                } else {
                    const int rr = r - 1;
                    const int bb_ = rr >> 10, s = rr & 1023;
                    const int h_ = (cg + 1) >> 6, dh = (cg + 1) & 63;
                    const size_t plane = ((size_t)(bb_ * NH + h_) * DH + dh) * SU2;
                    bsplit2(p1, c1, ph, pl);
                    VtHO[plane + (s >> 1)] = ph;
                    VtLO[plane + (s >> 1)] = pl;
                    bsplit2(p3, c3, ph, pl);
                    VtHO[plane + (s >> 1) + 4] = ph;
                    VtLO[plane + (s >> 1) + 4] = pl;
                }
            }
        }
    }
}

// ---------------------------------------------------------------------------
// Flash attention (round-13 exact, measured 247.7us): bf16x3, pre-packed
// operands, cp.async 2-stage, register-direct P fragments.
// ---------------------------------------------------------------------------
#define A2_LDK 36
#define A2_TILE (64 * A2_LDK)
#define A2_STAGE (4 * A2_TILE)
#define A2_MSK (2 * A2_STAGE)
#define A2_SMEM ((A2_MSK + 32) * 4)

__global__ void __launch_bounds__(256, 1) attn_bf16_kernel(
    const uint32_t* __restrict__ Qh, const uint32_t* __restrict__ Ql,
    const uint32_t* __restrict__ Kh, const uint32_t* __restrict__ Kl,
    const uint32_t* __restrict__ VtH, const uint32_t* __restrict__ VtL,
    const unsigned char* __restrict__ kpm,
    uint32_t* __restrict__ Oh, uint32_t* __restrict__ Ol)
{
    extern __shared__ uint32_t su[];

    const int b   = blockIdx.z;
    const int h   = blockIdx.y;
    const int qt  = gridDim.x - 1 - blockIdx.x;   // heavy tiles first
    const int tid = threadIdx.x;
    const int w    = tid >> 5;
    const int lane = tid & 31;
    const int gi = lane >> 2;
    const int t4 = lane & 3;

    const int q0   = qt * 128;
    const int row0 = q0 + w * 16 + gi;

    const float scale = 0.125f;
    const float NEG = -1e30f;

    uint32_t qh[4][4], ql[4][4];
    {
        const uint32_t* q0h = Qh + (size_t)(b * S_LEN + row0) * DU + h * 32;
        const uint32_t* q1h = q0h + 8 * DU;
        const uint32_t* q0l = Ql + (size_t)(b * S_LEN + row0) * DU + h * 32;
        const uint32_t* q1l = q0l + 8 * DU;
        #pragma unroll
        for (int kc = 0; kc < 4; kc++) {
            qh[kc][0] = q0h[kc * 8 + t4];
            qh[kc][1] = q1h[kc * 8 + t4];
            qh[kc][2] = q0h[kc * 8 + t4 + 4];
            qh[kc][3] = q1h[kc * 8 + t4 + 4];
            ql[kc][0] = q0l[kc * 8 + t4];
            ql[kc][1] = q1l[kc * 8 + t4];
            ql[kc][2] = q0l[kc * 8 + t4 + 4];
            ql[kc][3] = q1l[kc * 8 + t4 + 4];
        }
    }

    float oc[8][4];
    #pragma unroll
    for (int nt = 0; nt < 8; nt++)
        #pragma unroll
        for (int i = 0; i < 4; i++) oc[nt][i] = 0.0f;
    float m0 = NEG, m1 = NEG, l0 = 0.0f, l1 = 0.0f;

    const int ldr = tid >> 2;
    const int seg = tid & 3;
    const uint32_t smbase = (uint32_t)__cvta_generic_to_shared(su);
    const uint32_t dsto = (uint32_t)(ldr * A2_LDK + seg * 8) * 4;

    const uint32_t* khg = Kh + (size_t)(b * S_LEN + ldr) * DU + h * 32 + seg * 8;
    const uint32_t* klg = Kl + (size_t)(b * S_LEN + ldr) * DU + h * 32 + seg * 8;
    const uint32_t* vhg = VtH + ((size_t)(b * NH + h) * DH + ldr) * SU2 + seg * 8;
    const uint32_t* vlg = VtL + ((size_t)(b * NH + h) * DH + ldr) * SU2 + seg * 8;
    const size_t kstep = (size_t)DU;

    auto load_tile = [&](int st, int kt) {
        const int k0 = kt * 64;
        const uint32_t sb = smbase + (uint32_t)st * (A2_STAGE * 4) + dsto;
        cpa16(sb,                     khg + (size_t)k0 * kstep);
        cpa16(sb + 16,                khg + (size_t)k0 * kstep + 4);
        cpa16(sb + A2_TILE * 4,       klg + (size_t)k0 * kstep);
        cpa16(sb + A2_TILE * 4 + 16,  klg + (size_t)k0 * kstep + 4);
        cpa16(sb + A2_TILE * 8,       vhg + k0 / 2);
        cpa16(sb + A2_TILE * 8 + 16,  vhg + k0 / 2 + 4);
        cpa16(sb + A2_TILE * 12,      vlg + k0 / 2);
        cpa16(sb + A2_TILE * 12 + 16, vlg + k0 / 2 + 4);
        if (tid < 4)
            cpa16(smbase + (A2_MSK + st * 16) * 4 + tid * 16,
                  kpm + (size_t)b * S_LEN + k0 + tid * 16);
    };

    const int ktiles = 2 * qt + 2;

    load_tile(0, 0);
    CP_COMMIT();
    load_tile(1, 1);
    CP_COMMIT();

    for (int kt = 0; kt < ktiles; kt++) {
        const int k0 = kt * 64;
        if (kt + 1 < ktiles) CP_WAIT1(); else CP_WAIT0();
        __syncthreads();

        const uint32_t* St  = su + (kt & 1) * A2_STAGE;
        const uint32_t* Ksh = St;
        const uint32_t* Ksl = St + A2_TILE;
        const uint32_t* Vsh = St + 2 * A2_TILE;
        const uint32_t* Vsl = St + 3 * A2_TILE;
        const unsigned char* mb = (const unsigned char*)(su + A2_MSK + (kt & 1) * 16);

        float sc[8][4];
        #pragma unroll
        for (int nt = 0; nt < 8; nt++)
            #pragma unroll
            for (int i = 0; i < 4; i++) sc[nt][i] = 0.0f;

        #pragma unroll
        for (int kc = 0; kc < 4; kc++) {
            uint32_t bh[8][2], bl[8][2];
            #pragma unroll
            for (int nt = 0; nt < 8; nt++) {
                const int kr = (nt * 8 + gi) * A2_LDK + kc * 8 + t4;
                bh[nt][0] = Ksh[kr];
                bh[nt][1] = Ksh[kr + 4];
                bl[nt][0] = Ksl[kr];
                bl[nt][1] = Ksl[kr + 4];
            }
            #pragma unroll
            for (int nt = 0; nt < 8; nt++) mma_bf16(sc[nt], ql[kc], bh[nt][0], bh[nt][1]);
            #pragma unroll
            for (int nt = 0; nt < 8; nt++) mma_bf16(sc[nt], qh[kc], bl[nt][0], bl[nt][1]);
            #pragma unroll
            for (int nt = 0; nt < 8; nt++) mma_bf16(sc[nt], qh[kc], bh[nt][0], bh[nt][1]);
        }

        const bool needc = (k0 + 63) > row0;
        float rm0 = NEG, rm1 = NEG;
        #pragma unroll
        for (int nt = 0; nt < 8; nt++) {
            const int col = k0 + nt * 8 + 2 * t4;
            const float mg0 = mb[nt * 8 + 2 * t4]     ? NEG : 0.0f;
            const float mg1 = mb[nt * 8 + 2 * t4 + 1] ? NEG : 0.0f;
            float v0 = sc[nt][0] * scale + mg0;
            float v1 = sc[nt][1] * scale + mg1;
            float v2 = sc[nt][2] * scale + mg0;
            float v3 = sc[nt][3] * scale + mg1;
            if (needc) {
                if (col     > row0)     v0 = NEG;
                if (col + 1 > row0)     v1 = NEG;
                if (col     > row0 + 8) v2 = NEG;
                if (col + 1 > row0 + 8) v3 = NEG;
            }
            sc[nt][0] = v0; sc[nt][1] = v1; sc[nt][2] = v2; sc[nt][3] = v3;
            rm0 = fmaxf(rm0, fmaxf(v0, v1));
            rm1 = fmaxf(rm1, fmaxf(v2, v3));
        }
        rm0 = fmaxf(rm0, __shfl_xor_sync(0xffffffffu, rm0, 1, 4));
        rm0 = fmaxf(rm0, __shfl_xor_sync(0xffffffffu, rm0, 2, 4));
        rm1 = fmaxf(rm1, __shfl_xor_sync(0xffffffffu, rm1, 1, 4));
        rm1 = fmaxf(rm1, __shfl_xor_sync(0xffffffffu, rm1, 2, 4));

        const float mn0 = fmaxf(m0, rm0);
        const float mn1 = fmaxf(m1, rm1);
        const float cr0 = __expf(m0 - mn0);
        const float cr1 = __expf(m1 - mn1);

        float ps0 = 0.0f, ps1 = 0.0f;
        #pragma unroll
        for (int nt = 0; nt < 8; nt++) {
            const float e0 = __expf(sc[nt][0] - mn0);
            const float e1 = __expf(sc[nt][1] - mn0);
            const float e2 = __expf(sc[nt][2] - mn1);
            const float e3 = __expf(sc[nt][3] - mn1);
            sc[nt][0] = e0; sc[nt][1] = e1; sc[nt][2] = e2; sc[nt][3] = e3;
            ps0 += e0 + e1;
            ps1 += e2 + e3;
        }
        ps0 += __shfl_xor_sync(0xffffffffu, ps0, 1, 4);
        ps0 += __shfl_xor_sync(0xffffffffu, ps0, 2, 4);
        ps1 += __shfl_xor_sync(0xffffffffu, ps1, 1, 4);
        ps1 += __shfl_xor_sync(0xffffffffu, ps1, 2, 4);

        l0 = l0 * cr0 + ps0;  m0 = mn0;
        l1 = l1 * cr1 + ps1;  m1 = mn1;

        #pragma unroll
        for (int nt = 0; nt < 8; nt++) {
            oc[nt][0] *= cr0; oc[nt][1] *= cr0;
            oc[nt][2] *= cr1; oc[nt][3] *= cr1;
        }

        // ---- O += P V (bf16 x3): P fragments built directly in registers ----
        #pragma unroll
        for (int kc = 0; kc < 4; kc++) {
            uint32_t ah[4], al[4];
            bsplit2(sc[2 * kc][0],     sc[2 * kc][1],     ah[0], al[0]);
            bsplit2(sc[2 * kc][2],     sc[2 * kc][3],     ah[1], al[1]);
            bsplit2(sc[2 * kc + 1][0], sc[2 * kc + 1][1], ah[2], al[2]);
            bsplit2(sc[2 * kc + 1][2], sc[2 * kc + 1][3], ah[3], al[3]);

            uint32_t bh[8][2], bl[8][2];
            #pragma unroll
            for (int nt = 0; nt < 8; nt++) {
                const int vr = (nt * 8 + gi) * A2_LDK + kc * 8 + t4;
                bh[nt][0] = Vsh[vr];
                bh[nt][1] = Vsh[vr + 4];
                bl[nt][0] = Vsl[vr];
                bl[nt][1] = Vsl[vr + 4];
            }
            #pragma unroll
            for (int nt = 0; nt < 8; nt++) mma_bf16(oc[nt], al, bh[nt][0], bh[nt][1]);
            #pragma unroll
            for (int nt = 0; nt < 8; nt++) mma_bf16(oc[nt], ah, bl[nt][0], bl[nt][1]);
            #pragma unroll
            for (int nt = 0; nt < 8; nt++) mma_bf16(oc[nt], ah, bh[nt][0], bh[nt][1]);
        }

        __syncthreads();
        if (kt + 2 < ktiles) {
            load_tile(kt & 1, kt + 2);
            CP_COMMIT();
        }
    }

    const float inv0 = 1.0f / l0;
    const float inv1 = 1.0f / l1;
    uint32_t* o0h = Oh + (size_t)(b * S_LEN + row0) * DU + h * 32;
    uint32_t* o0l = Ol + (size_t)(b * S_LEN + row0) * DU + h * 32;
    uint32_t* o1h = o0h + 8 * DU;
    uint32_t* o1l = o0l + 8 * DU;
    #pragma unroll
    for (int nt = 0; nt < 8; nt++) {
        uint32_t ph, pl;
        bsplit2(oc[nt][0] * inv0, oc[nt][1] * inv0, ph, pl);
        o0h[nt * 4 + t4] = ph;
        o0l[nt * 4 + t4] = pl;
        bsplit2(oc[nt][2] * inv1, oc[nt][3] * inv1, ph, pl);
        o1h[nt * 4 + t4] = ph;
        o1l[nt * 4 + t4] = pl;
    }
}

// ---------------------------------------------------------------------------
// Launch
// ---------------------------------------------------------------------------
extern "C" void kernel_launch(void* const* d_in, const int* in_sizes, int n_in,
                              void* d_out, int out_size)
{
    const float* q    = (const float*)d_in[0];
    const float* k    = (const float*)d_in[1];
    const float* v    = (const float*)d_in[2];
    const unsigned char* kpm = (const unsigned char*)d_in[3];
    const float* Wq = (const float*)d_in[4];
    const float* bq = (const float*)d_in[5];
    const float* Wk = (const float*)d_in[6];
    const float* bk = (const float*)d_in[7];
    const float* Wv = (const float*)d_in[8];
    const float* bv = (const float*)d_in[9];
    const float* Wo = (const float*)d_in[10];
    const float* bo = (const float*)d_in[11];
    float* out = (float*)d_out;

    void *pAh, *pAl, *pWh, *pWl, *pQh, *pQl, *pKh, *pKl, *pVh, *pVl, *pOh, *pOl;
    cudaGetSymbolAddress(&pAh, g_Ahp);
    cudaGetSymbolAddress(&pAl, g_Alp);
    cudaGetSymbolAddress(&pWh, g_Whp);
    cudaGetSymbolAddress(&pWl, g_Wlp);
    cudaGetSymbolAddress(&pQh, g_Qh);
    cudaGetSymbolAddress(&pQl, g_Ql);
    cudaGetSymbolAddress(&pKh, g_Kh);
    cudaGetSymbolAddress(&pKl, g_Kl);
    cudaGetSymbolAddress(&pVh, g_VtH);
    cudaGetSymbolAddress(&pVl, g_VtL);
    cudaGetSymbolAddress(&pOh, g_Oh);
    cudaGetSymbolAddress(&pOl, g_Ol);

    cudaFuncSetAttribute(attn_bf16_kernel,
                         cudaFuncAttributeMaxDynamicSharedMemorySize, A2_SMEM);
    cudaFuncSetAttribute(gemm9_bf16,
                         cudaFuncAttributeMaxDynamicSharedMemorySize, G4_SMEM);

    // 1) pre-split weights + raw q/k/v activations
    dim3 wgrid(DD / 1024, 4);
    split_weights_kernel<<<wgrid, 256>>>(Wq, Wk, Wv, Wo,
                                         (uint32_t*)pWh, (uint32_t*)pWl);
    dim3 sgrid((M_ROWS * D_MODEL) / 1024, 3);
    split_acts_kernel<<<sgrid, 256>>>(q, k, v,
                                      (uint32_t*)pAh, (uint32_t*)pAl);

    // 2) fused Q/K/V projections -> packed (V transposed)
    dim3 ggrid(D_MODEL / 128, M_ROWS / 128, 3);
    gemm9_bf16<<<ggrid, 256, G4_SMEM>>>(
        (const uint32_t*)pAh, (const uint32_t*)pAl,
        (const uint32_t*)pWh, (const uint32_t*)pWl,
        bq, bk, bv,
        (uint32_t*)pQh, (uint32_t*)pQl,
        (uint32_t*)pKh, (uint32_t*)pKl,
        (uint32_t*)pVh, (uint32_t*)pVl,
        nullptr, 0, 0);

    // 3) attention -> packed Ao
    dim3 agrid(S_LEN / 128, NH, BATCH);
    attn_bf16_kernel<<<agrid, 256, A2_SMEM>>>(
        (const uint32_t*)pQh, (const uint32_t*)pQl,
        (const uint32_t*)pKh, (const uint32_t*)pKl,
        (const uint32_t*)pVh, (const uint32_t*)pVl,
        kpm,
        (uint32_t*)pOh, (uint32_t*)pOl);

    // 4) output projection (weight slab 3) -> fp32 out
    dim3 ogrid(D_MODEL / 128, M_ROWS / 128, 1);
    gemm9_bf16<<<ogrid, 256, G4_SMEM>>>(
        (const uint32_t*)pOh, (const uint32_t*)pOl,
        (const uint32_t*)pWh, (const uint32_t*)pWl,
        bo, bo, bo,
        nullptr, nullptr, nullptr, nullptr, nullptr, nullptr,
        out, 3, 1);
}